// round 10
// baseline (speedup 1.0000x reference)
#include <cuda_runtime.h>

#define S 1024
#define NB 4
#define PLANE (S * S)
#define TEXELS (NB * PLANE)   // 4M texels
#define EPS 1e-8f

// Fill tile geometry: 30x30 outputs; iter1 = 32x32 (exactly one warp of
// lanes wide); input halo 34x34. smem = 35.4 KB -> 5 blocks/SM.
#define TW 30
#define IW 34
#define I1W 33           // iter1 stride (32 cols + 1 pad)
#define GT 35            // ceil(1024/30)

// Scratch: 64 MB accumulator (rgb + weight).
__device__ float4 g_acc[TEXELS];

// Vectorized L2 reduction: one 16B atomic add instead of 4 scalar atomicAdds.
__device__ __forceinline__ void red_add_v4(float4* addr, float a, float b, float c, float d) {
    asm volatile("red.global.add.v4.f32 [%0], {%1, %2, %3, %4};"
                 :: "l"(addr), "f"(a), "f"(b), "f"(c), "f"(d)
                 : "memory");
}

// ---------------------------------------------------------------------------
// Bilinear splat for ONE image (n), 2 adjacent pixels per thread.
// _rn intrinsics are LOAD-BEARING: reference rounds mul/sub separately;
// FMA contraction of v = 1023 - y*1023 flips floor() -> 1e-3 rel_err.
// ---------------------------------------------------------------------------
__device__ __forceinline__ void splat_one(float4* accn, float tx, float ty,
                                          float r, float g, float b) {
    float u = __fmul_rn(tx, 1023.0f);
    float v = __fsub_rn(1023.0f, __fmul_rn(ty, 1023.0f));
    float x0f = floorf(u), y0f = floorf(v);
    float fx = __fsub_rn(u, x0f);
    float fy = __fsub_rn(v, y0f);
    int x0 = (int)x0f, y0 = (int)y0f;
    int x1 = x0 + 1,   y1 = y0 + 1;

    float gx = __fsub_rn(1.0f, fx);
    float gy = __fsub_rn(1.0f, fy);
    float w00 = __fmul_rn(gx, gy);
    float w10 = __fmul_rn(fx, gy);
    float w01 = __fmul_rn(gx, fy);
    float w11 = __fmul_rn(fx, fy);

    #define CORNER(XI, YI, WT) do {                                         \
        int xi = (XI), yi = (YI);                                           \
        float wt = (WT);                                                    \
        bool valid = ((unsigned)xi < (unsigned)S) &&                        \
                     ((unsigned)yi < (unsigned)S);                          \
        wt = valid ? wt : 0.f;                                              \
        int xc = min(max(xi, 0), S - 1);                                    \
        int yc = min(max(yi, 0), S - 1);                                    \
        red_add_v4(accn + yc * S + xc,                                      \
                   __fmul_rn(r, wt), __fmul_rn(g, wt),                      \
                   __fmul_rn(b, wt), wt);                                   \
    } while (0)

    CORNER(x0, y0, w00);
    CORNER(x1, y0, w10);
    CORNER(x0, y1, w01);
    CORNER(x1, y1, w11);
    #undef CORNER
}

__global__ void splat_kernel(const float* __restrict__ img,
                             const float4* __restrict__ uv2, int n) {
    int tid = blockIdx.x * blockDim.x + threadIdx.x;   // 0 .. 512K-1
    int hw = tid << 1;                                 // even pixel in image n

    float4 t = __ldg(uv2 + ((n * PLANE) >> 1) + tid);  // (u0,v0,u1,v1)
    const float* base = img + (size_t)n * 3 * PLANE + hw;
    float2 rr = *(const float2*)(base);
    float2 gg = *(const float2*)(base + PLANE);
    float2 bb = *(const float2*)(base + 2 * PLANE);

    float4* accn = g_acc + n * PLANE;
    splat_one(accn, t.x, t.y, rr.x, gg.x, bb.x);
    splat_one(accn, t.z, t.w, rr.y, gg.y, bb.y);
}

// ---------------------------------------------------------------------------
// Fused normalize + 2 hole-fill iterations for ONE image (n).
// Rolling-register vertical window; invariant p == tex*m, holes carry 0:
//   nsum = box3(p), ncnt = box3(m)
//   out = m ? p : (ncnt>0 ? nsum/ncnt : 0);  out_m = m | (ncnt>0)
// Reciprocal-multiply divisions (MUFU.RCP): budget 1e-3, we sit at ~5e-8.
// ---------------------------------------------------------------------------
__device__ __forceinline__ float4 add3(float4 a, float4 b, float4 c) {
    return make_float4(__fadd_rn(__fadd_rn(a.x, b.x), c.x),
                       __fadd_rn(__fadd_rn(a.y, b.y), c.y),
                       __fadd_rn(__fadd_rn(a.z, b.z), c.z),
                       __fadd_rn(__fadd_rn(a.w, b.w), c.w));
}

__device__ __forceinline__ float4 fin(float4 cen, float4 ns) {
    bool covered = cen.w > 0.f;
    float nm  = ns.w > 0.f ? 1.f : 0.f;
    float inv = nm * __frcp_rn(fmaxf(ns.w, EPS));   // 0 when hole has no neighbors
    float4 o;
    o.x = covered ? cen.x : ns.x * inv;
    o.y = covered ? cen.y : ns.y * inv;
    o.z = covered ? cen.z : ns.z * inv;
    o.w = fmaxf(cen.w, nm);
    return o;
}

__device__ __forceinline__ float4 hsum(const float4* buf, int stride, int row, int c) {
    const float4* p = buf + row * stride + c;
    return add3(p[0], p[1], p[2]);
}

__global__ __launch_bounds__(256, 5) void fill2x_kernel(float* __restrict__ otex, int n) {
    __shared__ float4 s_in[IW * IW];     // 34x34 normalized input + halo
    __shared__ float4 s_i1[32 * I1W];    // 32 rows x stride 33: iter-1 result

    int tx0 = blockIdx.x * TW;
    int ty0 = blockIdx.y * TW;
    const float4* __restrict__ base = g_acc + n * PLANE;
    int t    = threadIdx.x;   // 256 threads = 8 warps
    int lane = t & 31;
    int wg   = t >> 5;

    // ---- Load 34x34 halo, normalize: tex = acc/max(w,eps); p = tex*m; m = w>0
    for (int i = t; i < IW * IW; i += 256) {
        int r = i / IW, c = i - r * IW;
        int gx = tx0 + c - 2, gy = ty0 + r - 2;
        float4 v = make_float4(0.f, 0.f, 0.f, 0.f);
        if ((unsigned)gx < (unsigned)S && (unsigned)gy < (unsigned)S) {
            v = __ldg(base + gy * S + gx);
            float m  = v.w > 0.f ? 1.f : 0.f;
            float sc = m * __frcp_rn(fmaxf(v.w, EPS));
            v.x *= sc; v.y *= sc; v.z *= sc;
            v.w = m;
        }
        s_in[i] = v;
    }
    __syncthreads();

    // ---- Iter 1: lane -> col x = lane-1 (32 cols), warp wg -> 4 rows.
    {
        int y0 = wg * 4 - 1;
        int gx = tx0 + lane - 1;
        bool xin = (unsigned)gx < (unsigned)S;
        float4 hm = hsum(s_in, IW, y0 + 1, lane);
        float4 h0 = hsum(s_in, IW, y0 + 2, lane);
        #pragma unroll
        for (int k = 0; k < 4; k++) {
            int y = y0 + k;
            float4 hp  = hsum(s_in, IW, y + 3, lane);
            float4 cen = s_in[(y + 2) * IW + lane + 1];
            float4 o = fin(cen, add3(hm, h0, hp));
            int gy = ty0 + y;
            if (!xin || (unsigned)gy >= (unsigned)S)
                o = make_float4(0.f, 0.f, 0.f, 0.f);    // reference zero-pads
            s_i1[(y + 1) * I1W + lane] = o;
            hm = h0; h0 = hp;
        }
    }
    __syncthreads();

    // ---- Iter 2: lane -> out col x = lane (lane < TW), warp wg -> 4 rows.
    if (lane < TW) {
        int y0 = wg * 4;
        float4 hm = hsum(s_i1, I1W, y0,     lane);
        float4 h0 = hsum(s_i1, I1W, y0 + 1, lane);
        #pragma unroll
        for (int k = 0; k < 4; k++) {
            int y = y0 + k;
            if (y >= TW) break;
            float4 hp  = hsum(s_i1, I1W, y + 2, lane);
            float4 cen = s_i1[(y + 1) * I1W + lane + 1];
            float4 o = fin(cen, add3(hm, h0, hp));

            int gy = ty0 + y, gx = tx0 + lane;
            if ((unsigned)gy < (unsigned)S && (unsigned)gx < (unsigned)S) {
                float* op = otex + ((size_t)n * PLANE + (size_t)gy * S + gx) * 3;
                op[0] = o.x; op[1] = o.y; op[2] = o.z;
            }
            hm = h0; h0 = hp;
        }
    }
}

// ---------------------------------------------------------------------------
// Pipelined launch (fork/join under stream capture):
//   main stream:  memset -> splat(0) -> splat(1) -> splat(2) -> splat(3)
//   side stream:  fill(0..3), each gated on its splat's event; fills 0-2
//                 overlap splats 1-3 (disjoint resources: L2-atomic vs smem).
// Streams/events are created fresh each call (host-side only; kernel_launch
// runs ~3x total, never during graph replay). No device allocation.
// ---------------------------------------------------------------------------
extern "C" void kernel_launch(void* const* d_in, const int* in_sizes, int n_in,
                              void* d_out, int out_size) {
    const float*  img = (const float*)d_in[0];      // [4,3,1024,1024]
    const float4* uv2 = (const float4*)d_in[1];     // [4,1024,1024,2] as pairs
    float* out = (float*)d_out;                     // [4,1024,1024,3]

    cudaStream_t s1;
    cudaStreamCreateWithFlags(&s1, cudaStreamNonBlocking);
    cudaEvent_t evS[NB], evJoin;
    for (int i = 0; i < NB; i++) cudaEventCreateWithFlags(&evS[i], cudaEventDisableTiming);
    cudaEventCreateWithFlags(&evJoin, cudaEventDisableTiming);

    void* acc_ptr = 0;
    cudaGetSymbolAddress(&acc_ptr, g_acc);
    cudaMemsetAsync(acc_ptr, 0, (size_t)TEXELS * sizeof(float4), 0);

    dim3 fgrid(GT, GT, 1);
    for (int n = 0; n < NB; n++) {
        splat_kernel<<<(PLANE / 2) / 256, 256, 0, 0>>>(img, uv2, n);
        cudaEventRecord(evS[n], 0);
        cudaStreamWaitEvent(s1, evS[n], 0);
        fill2x_kernel<<<fgrid, 256, 0, s1>>>(out, n);
    }
    cudaEventRecord(evJoin, s1);
    cudaStreamWaitEvent(0, evJoin, 0);
}

// round 12
// speedup vs baseline: 1.0220x; 1.0220x over previous
#include <cuda_runtime.h>

#define S 1024
#define NB 4
#define PLANE (S * S)
#define TEXELS (NB * PLANE)   // 4M texels
#define EPS 1e-8f

// Fill tile geometry: 30x30 outputs; iter1 = 32x32 (one warp of lanes wide);
// input halo 34x34. smem = 35.4 KB -> 5 blocks/SM.
#define TW 30
#define IW 34
#define I1W 33           // iter1 stride (32 cols + 1 pad)
#define GT 35            // ceil(1024/30)

// Scratch: 64 MB accumulator (rgb + weight).
__device__ float4 g_acc[TEXELS];

// Vectorized L2 reduction: one 16B atomic add instead of 4 scalar atomicAdds.
__device__ __forceinline__ void red_add_v4(float4* addr, float a, float b, float c, float d) {
    asm volatile("red.global.add.v4.f32 [%0], {%1, %2, %3, %4};"
                 :: "l"(addr), "f"(a), "f"(b), "f"(c), "f"(d)
                 : "memory");
}

// ---------------------------------------------------------------------------
// Bilinear splat for TWO images [n0, n0+1], 2 adjacent pixels per thread.
// _rn intrinsics are LOAD-BEARING: reference rounds mul/sub separately;
// FMA contraction of v = 1023 - y*1023 flips floor() -> 1e-3 rel_err.
// ---------------------------------------------------------------------------
__device__ __forceinline__ void splat_one(float4* accn, float tx, float ty,
                                          float r, float g, float b) {
    float u = __fmul_rn(tx, 1023.0f);
    float v = __fsub_rn(1023.0f, __fmul_rn(ty, 1023.0f));
    float x0f = floorf(u), y0f = floorf(v);
    float fx = __fsub_rn(u, x0f);
    float fy = __fsub_rn(v, y0f);
    int x0 = (int)x0f, y0 = (int)y0f;
    int x1 = x0 + 1,   y1 = y0 + 1;

    float gx = __fsub_rn(1.0f, fx);
    float gy = __fsub_rn(1.0f, fy);
    float w00 = __fmul_rn(gx, gy);
    float w10 = __fmul_rn(fx, gy);
    float w01 = __fmul_rn(gx, fy);
    float w11 = __fmul_rn(fx, fy);

    #define CORNER(XI, YI, WT) do {                                         \
        int xi = (XI), yi = (YI);                                           \
        float wt = (WT);                                                    \
        bool valid = ((unsigned)xi < (unsigned)S) &&                        \
                     ((unsigned)yi < (unsigned)S);                          \
        wt = valid ? wt : 0.f;                                              \
        int xc = min(max(xi, 0), S - 1);                                    \
        int yc = min(max(yi, 0), S - 1);                                    \
        red_add_v4(accn + yc * S + xc,                                      \
                   __fmul_rn(r, wt), __fmul_rn(g, wt),                      \
                   __fmul_rn(b, wt), wt);                                   \
    } while (0)

    CORNER(x0, y0, w00);
    CORNER(x1, y0, w10);
    CORNER(x0, y1, w01);
    CORNER(x1, y1, w11);
    #undef CORNER
}

__global__ void splat_kernel(const float* __restrict__ img,
                             const float4* __restrict__ uv2, int n0) {
    int tid = blockIdx.x * blockDim.x + threadIdx.x;   // 0 .. 1M-1 (2 images)
    int p0 = tid << 1;                                 // even pixel in pair
    int n  = n0 + (p0 >> 20);
    int hw = p0 & (PLANE - 1);

    float4 t = __ldg(uv2 + ((n * PLANE) >> 1) + (hw >> 1));   // (u0,v0,u1,v1)
    const float* base = img + (size_t)n * 3 * PLANE + hw;
    float2 rr = *(const float2*)(base);
    float2 gg = *(const float2*)(base + PLANE);
    float2 bb = *(const float2*)(base + 2 * PLANE);

    float4* accn = g_acc + n * PLANE;
    splat_one(accn, t.x, t.y, rr.x, gg.x, bb.x);
    splat_one(accn, t.z, t.w, rr.y, gg.y, bb.y);
}

// ---------------------------------------------------------------------------
// Fused normalize + 2 hole-fill iterations (images n0 + blockIdx.z).
// Rolling-register vertical window; invariant p == tex*m, holes carry 0:
//   nsum = box3(p), ncnt = box3(m)
//   out = m ? p : (ncnt>0 ? nsum/ncnt : 0);  out_m = m | (ncnt>0)
// Reciprocal-multiply divisions (MUFU.RCP): budget 1e-3, we sit at ~5e-8.
// ---------------------------------------------------------------------------
__device__ __forceinline__ float4 add3(float4 a, float4 b, float4 c) {
    return make_float4(__fadd_rn(__fadd_rn(a.x, b.x), c.x),
                       __fadd_rn(__fadd_rn(a.y, b.y), c.y),
                       __fadd_rn(__fadd_rn(a.z, b.z), c.z),
                       __fadd_rn(__fadd_rn(a.w, b.w), c.w));
}

__device__ __forceinline__ float4 fin(float4 cen, float4 ns) {
    bool covered = cen.w > 0.f;
    float nm  = ns.w > 0.f ? 1.f : 0.f;
    float inv = nm * __frcp_rn(fmaxf(ns.w, EPS));   // 0 when hole has no neighbors
    float4 o;
    o.x = covered ? cen.x : ns.x * inv;
    o.y = covered ? cen.y : ns.y * inv;
    o.z = covered ? cen.z : ns.z * inv;
    o.w = fmaxf(cen.w, nm);
    return o;
}

__device__ __forceinline__ float4 hsum(const float4* buf, int stride, int row, int c) {
    const float4* p = buf + row * stride + c;
    return add3(p[0], p[1], p[2]);
}

__global__ __launch_bounds__(256, 5) void fill2x_kernel(float* __restrict__ otex, int n0) {
    __shared__ float4 s_in[IW * IW];     // 34x34 normalized input + halo
    __shared__ float4 s_i1[32 * I1W];    // 32 rows x stride 33: iter-1 result

    int n   = n0 + blockIdx.z;
    int tx0 = blockIdx.x * TW;
    int ty0 = blockIdx.y * TW;
    const float4* __restrict__ base = g_acc + n * PLANE;
    int t    = threadIdx.x;   // 256 threads = 8 warps
    int lane = t & 31;
    int wg   = t >> 5;

    // ---- Load 34x34 halo, normalize: tex = acc/max(w,eps); p = tex*m; m = w>0
    for (int i = t; i < IW * IW; i += 256) {
        int r = i / IW, c = i - r * IW;
        int gx = tx0 + c - 2, gy = ty0 + r - 2;
        float4 v = make_float4(0.f, 0.f, 0.f, 0.f);
        if ((unsigned)gx < (unsigned)S && (unsigned)gy < (unsigned)S) {
            v = __ldg(base + gy * S + gx);
            float m  = v.w > 0.f ? 1.f : 0.f;
            float sc = m * __frcp_rn(fmaxf(v.w, EPS));
            v.x *= sc; v.y *= sc; v.z *= sc;
            v.w = m;
        }
        s_in[i] = v;
    }
    __syncthreads();

    // ---- Iter 1: lane -> col x = lane-1 (32 cols), warp wg -> 4 rows.
    {
        int y0 = wg * 4 - 1;
        int gx = tx0 + lane - 1;
        bool xin = (unsigned)gx < (unsigned)S;
        float4 hm = hsum(s_in, IW, y0 + 1, lane);
        float4 h0 = hsum(s_in, IW, y0 + 2, lane);
        #pragma unroll
        for (int k = 0; k < 4; k++) {
            int y = y0 + k;
            float4 hp  = hsum(s_in, IW, y + 3, lane);
            float4 cen = s_in[(y + 2) * IW + lane + 1];
            float4 o = fin(cen, add3(hm, h0, hp));
            int gy = ty0 + y;
            if (!xin || (unsigned)gy >= (unsigned)S)
                o = make_float4(0.f, 0.f, 0.f, 0.f);    // reference zero-pads
            s_i1[(y + 1) * I1W + lane] = o;
            hm = h0; h0 = hp;
        }
    }
    __syncthreads();

    // ---- Iter 2: lane -> out col x = lane (lane < TW), warp wg -> 4 rows.
    if (lane < TW) {
        int y0 = wg * 4;
        float4 hm = hsum(s_i1, I1W, y0,     lane);
        float4 h0 = hsum(s_i1, I1W, y0 + 1, lane);
        #pragma unroll
        for (int k = 0; k < 4; k++) {
            int y = y0 + k;
            if (y >= TW) break;
            float4 hp  = hsum(s_i1, I1W, y + 2, lane);
            float4 cen = s_i1[(y + 1) * I1W + lane + 1];
            float4 o = fin(cen, add3(hm, h0, hp));

            int gy = ty0 + y, gx = tx0 + lane;
            if ((unsigned)gy < (unsigned)S && (unsigned)gx < (unsigned)S) {
                float* op = otex + ((size_t)n * PLANE + (size_t)gy * S + gx) * 3;
                op[0] = o.x; op[1] = o.y; op[2] = o.z;
            }
            hm = h0; h0 = hp;
        }
    }
}

// ---------------------------------------------------------------------------
// Half-granularity pipeline. CAPTURE RULE (R11 failure): a side stream may
// only receive work AFTER it is forked into the capture via
// cudaStreamWaitEvent on an event recorded in the capturing stream.
//   stream0: evStart -> memsetA -> splatA(0,1) -> [wait evMB] splatB(2,3)
//   s1:      [wait evStart] memsetB (|| splatA) -> [wait evSA] fillA(0,1)
//            -> [wait evSB] fillB(2,3) -> evJoin
//   stream0: [wait evJoin]
// ---------------------------------------------------------------------------
extern "C" void kernel_launch(void* const* d_in, const int* in_sizes, int n_in,
                              void* d_out, int out_size) {
    const float*  img = (const float*)d_in[0];      // [4,3,1024,1024]
    const float4* uv2 = (const float4*)d_in[1];     // [4,1024,1024,2] as pairs
    float* out = (float*)d_out;                     // [4,1024,1024,3]

    cudaStream_t s1;
    cudaStreamCreateWithFlags(&s1, cudaStreamNonBlocking);
    cudaEvent_t evStart, evMB, evSA, evSB, evJoin;
    cudaEventCreateWithFlags(&evStart, cudaEventDisableTiming);
    cudaEventCreateWithFlags(&evMB, cudaEventDisableTiming);
    cudaEventCreateWithFlags(&evSA, cudaEventDisableTiming);
    cudaEventCreateWithFlags(&evSB, cudaEventDisableTiming);
    cudaEventCreateWithFlags(&evJoin, cudaEventDisableTiming);

    char* acc_ptr = 0;
    cudaGetSymbolAddress((void**)&acc_ptr, g_acc);
    const size_t half_bytes = (size_t)(TEXELS / 2) * sizeof(float4);

    // Fork s1 into the capture BEFORE putting any work on it.
    cudaEventRecord(evStart, 0);
    cudaStreamWaitEvent(s1, evStart, 0);

    // memsetA (images 0,1) on stream0; memsetB (2,3) on s1, overlapping splatA.
    cudaMemsetAsync(acc_ptr, 0, half_bytes, 0);
    cudaMemsetAsync(acc_ptr + half_bytes, 0, half_bytes, s1);
    cudaEventRecord(evMB, s1);

    const int sgrid = PLANE / 256;       // 2 images, 2 px/thread -> 4096 blocks
    dim3 fgrid(GT, GT, 2);

    splat_kernel<<<sgrid, 256, 0, 0>>>(img, uv2, 0);
    cudaEventRecord(evSA, 0);

    cudaStreamWaitEvent(0, evMB, 0);
    splat_kernel<<<sgrid, 256, 0, 0>>>(img, uv2, 2);
    cudaEventRecord(evSB, 0);

    cudaStreamWaitEvent(s1, evSA, 0);
    fill2x_kernel<<<fgrid, 256, 0, s1>>>(out, 0);    // overlaps splatB
    cudaStreamWaitEvent(s1, evSB, 0);
    fill2x_kernel<<<fgrid, 256, 0, s1>>>(out, 2);

    cudaEventRecord(evJoin, s1);
    cudaStreamWaitEvent(0, evJoin, 0);
}

// round 14
// speedup vs baseline: 1.0296x; 1.0075x over previous
#include <cuda_runtime.h>

#define S 1024
#define NB 4
#define PLANE (S * S)
#define TEXELS (NB * PLANE)   // 4M texels
#define EPS 1e-8f

// Fill tile: 30x30 outputs; iter1 = 32 cols (one warp of lanes) x rows;
// input halo 34x34 (18.5 KB smem only).
#define TW 30
#define IW 34
#define GT 35            // ceil(1024/30)

// Scratch: 64 MB accumulator (rgb + weight).
__device__ float4 g_acc[TEXELS];

// Vectorized L2 reduction: one 16B atomic add instead of 4 scalar atomicAdds.
__device__ __forceinline__ void red_add_v4(float4* addr, float a, float b, float c, float d) {
    asm volatile("red.global.add.v4.f32 [%0], {%1, %2, %3, %4};"
                 :: "l"(addr), "f"(a), "f"(b), "f"(c), "f"(d)
                 : "memory");
}

// ---------------------------------------------------------------------------
// Bilinear splat, 2 adjacent pixels per thread (at the REDG floor).
// _rn intrinsics are LOAD-BEARING: reference rounds mul/sub separately;
// FMA contraction of v = 1023 - y*1023 flips floor() -> 1e-3 rel_err.
// ---------------------------------------------------------------------------
__device__ __forceinline__ void splat_one(float4* accn, float tx, float ty,
                                          float r, float g, float b) {
    float u = __fmul_rn(tx, 1023.0f);
    float v = __fsub_rn(1023.0f, __fmul_rn(ty, 1023.0f));
    float x0f = floorf(u), y0f = floorf(v);
    float fx = __fsub_rn(u, x0f);
    float fy = __fsub_rn(v, y0f);
    int x0 = (int)x0f, y0 = (int)y0f;
    int x1 = x0 + 1,   y1 = y0 + 1;

    float gx = __fsub_rn(1.0f, fx);
    float gy = __fsub_rn(1.0f, fy);
    float w00 = __fmul_rn(gx, gy);
    float w10 = __fmul_rn(fx, gy);
    float w01 = __fmul_rn(gx, fy);
    float w11 = __fmul_rn(fx, fy);

    #define CORNER(XI, YI, WT) do {                                         \
        int xi = (XI), yi = (YI);                                           \
        float wt = (WT);                                                    \
        bool valid = ((unsigned)xi < (unsigned)S) &&                        \
                     ((unsigned)yi < (unsigned)S);                          \
        wt = valid ? wt : 0.f;                                              \
        int xc = min(max(xi, 0), S - 1);                                    \
        int yc = min(max(yi, 0), S - 1);                                    \
        red_add_v4(accn + yc * S + xc,                                      \
                   __fmul_rn(r, wt), __fmul_rn(g, wt),                      \
                   __fmul_rn(b, wt), wt);                                   \
    } while (0)

    CORNER(x0, y0, w00);
    CORNER(x1, y0, w10);
    CORNER(x0, y1, w01);
    CORNER(x1, y1, w11);
    #undef CORNER
}

__global__ void splat_kernel(const float* __restrict__ img,
                             const float4* __restrict__ uv2) {
    int tid = blockIdx.x * blockDim.x + threadIdx.x;   // 0 .. 2M-1
    int p0 = tid << 1;                                 // even pixel index
    int n  = p0 >> 20;
    int hw = p0 & (PLANE - 1);

    float4 t = __ldg(uv2 + tid);                       // (u0,v0,u1,v1)
    const float* base = img + (size_t)n * 3 * PLANE + hw;
    float2 rr = *(const float2*)(base);
    float2 gg = *(const float2*)(base + PLANE);
    float2 bb = *(const float2*)(base + 2 * PLANE);

    float4* accn = g_acc + n * PLANE;
    splat_one(accn, t.x, t.y, rr.x, gg.x, bb.x);
    splat_one(accn, t.z, t.w, rr.y, gg.y, bb.y);
}

// ---------------------------------------------------------------------------
// Fused normalize + 2 hole-fill iterations. Iter-1 rolls through smem with
// registered hsums; iter-2 is PURE register/shuffle (no s_i1 buffer, no 2nd
// barrier). Each warp redundantly computes 6 iter-1 rows (3-row register
// window); lane L holds iter-1 col L-1; horizontal 3-sum and center come
// from shfl_down. All s_in ROW reads are clamped to IW-1: warp 7's last two
// loop steps feed only outputs masked by yy<TW (R13 fault: unclamped rows
// 34/35 read past the 34x34 tile).
//   nsum = box3(p), ncnt = box3(m); out = m ? p : (ncnt>0 ? nsum/ncnt : 0)
// ---------------------------------------------------------------------------
__device__ __forceinline__ float4 add3(float4 a, float4 b, float4 c) {
    return make_float4(__fadd_rn(__fadd_rn(a.x, b.x), c.x),
                       __fadd_rn(__fadd_rn(a.y, b.y), c.y),
                       __fadd_rn(__fadd_rn(a.z, b.z), c.z),
                       __fadd_rn(__fadd_rn(a.w, b.w), c.w));
}

__device__ __forceinline__ float4 fin(float4 cen, float4 ns) {
    bool covered = cen.w > 0.f;
    float nm  = ns.w > 0.f ? 1.f : 0.f;
    float inv = nm * __frcp_rn(fmaxf(ns.w, EPS));   // 0 when hole has no neighbors
    float4 o;
    o.x = covered ? cen.x : ns.x * inv;
    o.y = covered ? cen.y : ns.y * inv;
    o.z = covered ? cen.z : ns.z * inv;
    o.w = fmaxf(cen.w, nm);
    return o;
}

__device__ __forceinline__ float4 hsum(const float4* buf, int row, int c) {
    const float4* p = buf + row * IW + c;
    return add3(p[0], p[1], p[2]);
}

__device__ __forceinline__ float4 shfl_dn(float4 v, int d) {
    float4 o;
    o.x = __shfl_down_sync(0xffffffffu, v.x, d);
    o.y = __shfl_down_sync(0xffffffffu, v.y, d);
    o.z = __shfl_down_sync(0xffffffffu, v.z, d);
    o.w = __shfl_down_sync(0xffffffffu, v.w, d);
    return o;
}

__global__ __launch_bounds__(256, 5) void fill2x_kernel(float* __restrict__ otex) {
    __shared__ float4 s_in[IW * IW];     // 34x34 normalized input + halo

    int n   = blockIdx.z;
    int tx0 = blockIdx.x * TW;
    int ty0 = blockIdx.y * TW;
    const float4* __restrict__ base = g_acc + n * PLANE;
    int t    = threadIdx.x;   // 256 threads = 8 warps
    int lane = t & 31;
    int wg   = t >> 5;

    // ---- Load 34x34 halo, normalize: tex = acc/max(w,eps); p = tex*m; m = w>0
    for (int i = t; i < IW * IW; i += 256) {
        int r = i / IW, c = i - r * IW;
        int gx = tx0 + c - 2, gy = ty0 + r - 2;
        float4 v = make_float4(0.f, 0.f, 0.f, 0.f);
        if ((unsigned)gx < (unsigned)S && (unsigned)gy < (unsigned)S) {
            v = __ldg(base + gy * S + gx);
            float m  = v.w > 0.f ? 1.f : 0.f;
            float sc = m * __frcp_rn(fmaxf(v.w, EPS));
            v.x *= sc; v.y *= sc; v.z *= sc;
            v.w = m;
        }
        s_in[i] = v;
    }
    __syncthreads();

    // ---- Warp wg: iter1 rows y = y0+j, j=0..5 (y0 = wg*4-1), col x = lane-1.
    //      3-row window (oa,ob,oc); from j>=2 emit iter2 row yy = y0+j-1.
    //      s_in(x,y) at row y+2, col x+2; hsum cols lane..lane+2 = x-1..x+1.
    {
        int y0 = wg * 4 - 1;
        int gx = tx0 + lane - 1;
        bool xin = (unsigned)gx < (unsigned)S;

        float4 hm = hsum(s_in, y0 + 1, lane);
        float4 h0 = hsum(s_in, y0 + 2, lane);
        float4 oa, ob, oc;

        #pragma unroll
        for (int j = 0; j < 6; j++) {
            int y = y0 + j;
            // Clamp rows: warp 7, j>=4 reads feed only yy>=30 (masked) outputs.
            int rh = min(y + 3, IW - 1);
            int rc = min(y + 2, IW - 1);
            float4 hp  = hsum(s_in, rh, lane);
            float4 cen = s_in[rc * IW + lane + 1];
            float4 o = fin(cen, add3(hm, h0, hp));
            int gy = ty0 + y;
            if (!xin || (unsigned)gy >= (unsigned)S)
                o = make_float4(0.f, 0.f, 0.f, 0.f);    // reference zero-pads
            hm = h0; h0 = hp;
            oa = ob; ob = oc; oc = o;

            if (j >= 2) {
                // iter2 row yy = y0 + j - 1; vertical 3-sum in registers
                float4 v  = add3(oa, ob, oc);
                // horizontal: cols lane-1..lane+1 = lanes lane..lane+2
                float4 ns = add3(v, shfl_dn(v, 1), shfl_dn(v, 2));
                float4 c2 = shfl_dn(ob, 1);             // center: col lane
                float4 outv = fin(c2, ns);

                int yy = y0 + j - 1;
                int gyy = ty0 + yy, gxx = tx0 + lane;
                if (lane < TW && yy < TW &&
                    (unsigned)gyy < (unsigned)S && (unsigned)gxx < (unsigned)S) {
                    float* op = otex + ((size_t)n * PLANE + (size_t)gyy * S + gxx) * 3;
                    op[0] = outv.x; op[1] = outv.y; op[2] = outv.z;
                }
            }
        }
    }
}

// ---------------------------------------------------------------------------
// Launch (monolithic — overlap condemned by R10/R12 evidence):
//   memset(acc) -> splat (2 px/thread) -> fused normalize+fill2x
// ---------------------------------------------------------------------------
extern "C" void kernel_launch(void* const* d_in, const int* in_sizes, int n_in,
                              void* d_out, int out_size) {
    const float*  img = (const float*)d_in[0];      // [4,3,1024,1024]
    const float4* uv2 = (const float4*)d_in[1];     // [4,1024,1024,2] as pairs
    float* out = (float*)d_out;                     // [4,1024,1024,3]

    void* acc_ptr = 0;
    cudaGetSymbolAddress(&acc_ptr, g_acc);
    cudaMemsetAsync(acc_ptr, 0, (size_t)TEXELS * sizeof(float4), 0);

    splat_kernel<<<(TEXELS / 2) / 256, 256>>>(img, uv2);

    dim3 grid(GT, GT, NB);
    fill2x_kernel<<<grid, 256>>>(out);
}

// round 15
// speedup vs baseline: 1.0629x; 1.0324x over previous
#include <cuda_runtime.h>

#define S 1024
#define NB 4
#define PLANE (S * S)
#define TEXELS (NB * PLANE)   // 4M texels
#define EPS 1e-8f

// Fill tile geometry: 30x30 outputs; iter1 = 32x32 (one warp of lanes wide);
// input halo 34x34. smem = 35.4 KB; regs capped to 42 -> 6 blocks/SM.
#define TW 30
#define IW 34
#define I1W 33           // iter1 stride (32 cols + 1 pad)
#define GT 35            // ceil(1024/30)

// Scratch: 64 MB accumulator (rgb + weight).
__device__ float4 g_acc[TEXELS];

// Vectorized L2 reduction: one 16B atomic add instead of 4 scalar atomicAdds.
__device__ __forceinline__ void red_add_v4(float4* addr, float a, float b, float c, float d) {
    asm volatile("red.global.add.v4.f32 [%0], {%1, %2, %3, %4};"
                 :: "l"(addr), "f"(a), "f"(b), "f"(c), "f"(d)
                 : "memory");
}

// ---------------------------------------------------------------------------
// Bilinear splat, 2 adjacent pixels per thread (at the L2 REDG floor).
// _rn intrinsics are LOAD-BEARING: reference rounds mul/sub separately;
// FMA contraction of v = 1023 - y*1023 flips floor() -> 1e-3 rel_err.
// ---------------------------------------------------------------------------
__device__ __forceinline__ void splat_one(float4* accn, float tx, float ty,
                                          float r, float g, float b) {
    float u = __fmul_rn(tx, 1023.0f);
    float v = __fsub_rn(1023.0f, __fmul_rn(ty, 1023.0f));
    float x0f = floorf(u), y0f = floorf(v);
    float fx = __fsub_rn(u, x0f);
    float fy = __fsub_rn(v, y0f);
    int x0 = (int)x0f, y0 = (int)y0f;
    int x1 = x0 + 1,   y1 = y0 + 1;

    float gx = __fsub_rn(1.0f, fx);
    float gy = __fsub_rn(1.0f, fy);
    float w00 = __fmul_rn(gx, gy);
    float w10 = __fmul_rn(fx, gy);
    float w01 = __fmul_rn(gx, fy);
    float w11 = __fmul_rn(fx, fy);

    #define CORNER(XI, YI, WT) do {                                         \
        int xi = (XI), yi = (YI);                                           \
        float wt = (WT);                                                    \
        bool valid = ((unsigned)xi < (unsigned)S) &&                        \
                     ((unsigned)yi < (unsigned)S);                          \
        wt = valid ? wt : 0.f;                                              \
        int xc = min(max(xi, 0), S - 1);                                    \
        int yc = min(max(yi, 0), S - 1);                                    \
        red_add_v4(accn + yc * S + xc,                                      \
                   __fmul_rn(r, wt), __fmul_rn(g, wt),                      \
                   __fmul_rn(b, wt), wt);                                   \
    } while (0)

    CORNER(x0, y0, w00);
    CORNER(x1, y0, w10);
    CORNER(x0, y1, w01);
    CORNER(x1, y1, w11);
    #undef CORNER
}

__global__ void splat_kernel(const float* __restrict__ img,
                             const float4* __restrict__ uv2) {
    int tid = blockIdx.x * blockDim.x + threadIdx.x;   // 0 .. 2M-1
    int p0 = tid << 1;                                 // even pixel index
    int n  = p0 >> 20;
    int hw = p0 & (PLANE - 1);

    float4 t = __ldg(uv2 + tid);                       // (u0,v0,u1,v1)
    const float* base = img + (size_t)n * 3 * PLANE + hw;
    float2 rr = *(const float2*)(base);
    float2 gg = *(const float2*)(base + PLANE);
    float2 bb = *(const float2*)(base + 2 * PLANE);

    float4* accn = g_acc + n * PLANE;
    splat_one(accn, t.x, t.y, rr.x, gg.x, bb.x);
    splat_one(accn, t.z, t.w, rr.y, gg.y, bb.y);
}

// ---------------------------------------------------------------------------
// Fused normalize + 2 hole-fill iterations (R9 structure — the proven best:
// rolling-register vertical window, s_i1 staging, no shuffles).
// Invariant: stored p == tex*m, holes carry 0, so both iterations are:
//   nsum = box3(p), ncnt = box3(m)
//   out = m ? p : (ncnt>0 ? nsum/ncnt : 0);  out_m = m | (ncnt>0)
// Reciprocal-multiply divisions (MUFU.RCP): budget 1e-3, we sit at ~5e-8.
// Launch bounds (256,6): cap regs at 42 so 6 blocks/SM fit the register file
// (48 regs allowed only 5). smem 35.4KB x 6 = 212KB <= 228KB.
// ---------------------------------------------------------------------------
__device__ __forceinline__ float4 add3(float4 a, float4 b, float4 c) {
    return make_float4(__fadd_rn(__fadd_rn(a.x, b.x), c.x),
                       __fadd_rn(__fadd_rn(a.y, b.y), c.y),
                       __fadd_rn(__fadd_rn(a.z, b.z), c.z),
                       __fadd_rn(__fadd_rn(a.w, b.w), c.w));
}

__device__ __forceinline__ float4 fin(float4 cen, float4 ns) {
    bool covered = cen.w > 0.f;
    float nm  = ns.w > 0.f ? 1.f : 0.f;
    float inv = nm * __frcp_rn(fmaxf(ns.w, EPS));   // 0 when hole has no neighbors
    float4 o;
    o.x = covered ? cen.x : ns.x * inv;
    o.y = covered ? cen.y : ns.y * inv;
    o.z = covered ? cen.z : ns.z * inv;
    o.w = fmaxf(cen.w, nm);
    return o;
}

__device__ __forceinline__ float4 hsum(const float4* buf, int stride, int row, int c) {
    const float4* p = buf + row * stride + c;
    return add3(p[0], p[1], p[2]);
}

__global__ __launch_bounds__(256, 6) void fill2x_kernel(float* __restrict__ otex) {
    __shared__ float4 s_in[IW * IW];     // 34x34 normalized input + halo
    __shared__ float4 s_i1[32 * I1W];    // 32 rows x stride 33: iter-1 result

    int n   = blockIdx.z;
    int tx0 = blockIdx.x * TW;
    int ty0 = blockIdx.y * TW;
    const float4* __restrict__ base = g_acc + n * PLANE;
    int t    = threadIdx.x;   // 256 threads = 8 warps
    int lane = t & 31;
    int wg   = t >> 5;

    // ---- Load 34x34 halo, normalize: tex = acc/max(w,eps); p = tex*m; m = w>0
    for (int i = t; i < IW * IW; i += 256) {
        int r = i / IW, c = i - r * IW;
        int gx = tx0 + c - 2, gy = ty0 + r - 2;
        float4 v = make_float4(0.f, 0.f, 0.f, 0.f);
        if ((unsigned)gx < (unsigned)S && (unsigned)gy < (unsigned)S) {
            v = __ldg(base + gy * S + gx);
            float m  = v.w > 0.f ? 1.f : 0.f;
            float sc = m * __frcp_rn(fmaxf(v.w, EPS));
            v.x *= sc; v.y *= sc; v.z *= sc;
            v.w = m;
        }
        s_in[i] = v;
    }
    __syncthreads();

    // ---- Iter 1: lane -> col x = lane-1 (32 cols), warp wg -> 4 rows
    //      y = wg*4-1 .. wg*4+2. s_in(x,y) at row y+2, col x+2;
    //      hsum over cols lane..lane+2 covers x-1..x+1. Rolling hm/h0/hp.
    {
        int y0 = wg * 4 - 1;
        int gx = tx0 + lane - 1;
        bool xin = (unsigned)gx < (unsigned)S;
        float4 hm = hsum(s_in, IW, y0 + 1, lane);
        float4 h0 = hsum(s_in, IW, y0 + 2, lane);
        #pragma unroll
        for (int k = 0; k < 4; k++) {
            int y = y0 + k;
            float4 hp  = hsum(s_in, IW, y + 3, lane);
            float4 cen = s_in[(y + 2) * IW + lane + 1];
            float4 o = fin(cen, add3(hm, h0, hp));
            int gy = ty0 + y;
            if (!xin || (unsigned)gy >= (unsigned)S)
                o = make_float4(0.f, 0.f, 0.f, 0.f);    // reference zero-pads
            s_i1[(y + 1) * I1W + lane] = o;
            hm = h0; h0 = hp;
        }
    }
    __syncthreads();

    // ---- Iter 2: lane -> out col x = lane (lane < TW), warp wg -> 4 rows.
    //      s_i1 col c holds x = c-1; hsum cols lane..lane+2 covers x-1..x+1.
    if (lane < TW) {
        int y0 = wg * 4;
        float4 hm = hsum(s_i1, I1W, y0,     lane);
        float4 h0 = hsum(s_i1, I1W, y0 + 1, lane);
        #pragma unroll
        for (int k = 0; k < 4; k++) {
            int y = y0 + k;
            if (y >= TW) break;
            float4 hp  = hsum(s_i1, I1W, y + 2, lane);
            float4 cen = s_i1[(y + 1) * I1W + lane + 1];
            float4 o = fin(cen, add3(hm, h0, hp));

            int gy = ty0 + y, gx = tx0 + lane;
            if ((unsigned)gy < (unsigned)S && (unsigned)gx < (unsigned)S) {
                float* op = otex + ((size_t)n * PLANE + (size_t)gy * S + gx) * 3;
                op[0] = o.x; op[1] = o.y; op[2] = o.z;
            }
            hm = h0; h0 = hp;
        }
    }
}

// ---------------------------------------------------------------------------
// Launch (monolithic — overlap condemned by R10/R12 evidence):
//   memset(acc) -> splat (2 px/thread) -> fused normalize+fill2x
// ---------------------------------------------------------------------------
extern "C" void kernel_launch(void* const* d_in, const int* in_sizes, int n_in,
                              void* d_out, int out_size) {
    const float*  img = (const float*)d_in[0];      // [4,3,1024,1024]
    const float4* uv2 = (const float4*)d_in[1];     // [4,1024,1024,2] as pairs
    float* out = (float*)d_out;                     // [4,1024,1024,3]

    void* acc_ptr = 0;
    cudaGetSymbolAddress(&acc_ptr, g_acc);
    cudaMemsetAsync(acc_ptr, 0, (size_t)TEXELS * sizeof(float4), 0);

    splat_kernel<<<(TEXELS / 2) / 256, 256>>>(img, uv2);

    dim3 grid(GT, GT, NB);
    fill2x_kernel<<<grid, 256>>>(out);
}